// round 13
// baseline (speedup 1.0000x reference)
#include <cuda_runtime.h>
#include <cstdint>

// T = 2000 tags, V = 20000 videos, D = 768, E_POS = E_NEG = 100000
// Output layout: [cls_score (V*T f32), labels (V*T f32)]
//
// R13 (serial phases; edge kernel rebuilt for latency hiding):
//   K1 zero_kernel   : 320MB evict-first stream (proven ~45us, DRAM floor)
//                      + resets all edge cursors (runs first each replay ->
//                      race-free lifecycle: zero resets, scatter fills,
//                      edge READS ONLY).
//   K2 scatter_kernel: bin edges by (tag, sub) with sub = i & 3. 8000
//                      counters -> ~25 atomics each.
//   K3 edge_kernel   : block per tag; 8 warps = 4 pairs; pair p owns
//                      sub-bin p. EACH WARP DOES HALF A ROW (3 float4/lane):
//                      halves the per-edge dependency chain and the register
//                      cost vs R3 (50 regs -> 5 blocks/SM -> 40 warps vs
//                      R3's 78 regs -> 3 blocks/SM -> 24 warps), keeping the
//                      double-buffer prefetch. Each half-warp atomicAdds its
//                      partial dot (two adds sum to the same score).

#define D_DIM    768
#define T_DIM    2000
#define BIN_SUB  4
#define SUB_CAP  64      // Poisson(25)/sub-bin; P(>64) ~ 4e-15 per bin

#define NCUR     (T_DIM * BIN_SUB)

__device__ int      g_cursor[NCUR];              // zero at module load
__device__ unsigned g_edges [NCUR * SUB_CAP];    // bit31=isPos, low=dst

// ---------------------------------------------------------------------------
__global__ void zero_kernel(float4* __restrict__ out, long long nvec) {
    long long i = (long long)blockIdx.x * blockDim.x + threadIdx.x;
    if (i < nvec)
        __stcs(&out[i], make_float4(0.f, 0.f, 0.f, 0.f));
    if (i < NCUR) g_cursor[(int)i] = 0;     // reset cursors for this replay
}

// ---------------------------------------------------------------------------
__global__ void scatter_kernel(const int* __restrict__ pos_src,
                               const int* __restrict__ pos_dst,
                               const int* __restrict__ neg_src,
                               const int* __restrict__ neg_dst,
                               int nPos, int nTot) {
    int i = blockIdx.x * blockDim.x + threadIdx.x;
    if (i < nTot) {
        int t; unsigned enc;
        if (i < nPos) { t = pos_src[i];        enc = (unsigned)pos_dst[i] | 0x80000000u; }
        else          { t = neg_src[i - nPos]; enc = (unsigned)neg_dst[i - nPos]; }
        int cidx = t * BIN_SUB + (i & (BIN_SUB - 1));
        int slot = atomicAdd(&g_cursor[cidx], 1);
        if (slot < SUB_CAP)
            g_edges[cidx * SUB_CAP + slot] = enc;
    }
}

// ---------------------------------------------------------------------------
// Block per tag; warp pair p = warp>>1 owns sub-bin p; half = warp&1 selects
// which half of the 768-dim row this warp covers (float4s half*96 + lane + k*32).
// Double-buffered prefetch of the next edge's half-row.
// ---------------------------------------------------------------------------
__global__ __launch_bounds__(256) void edge_kernel(
    const float* __restrict__ h_tag,
    const float* __restrict__ h_video,
    float*       __restrict__ cls,
    float*       __restrict__ labels)
{
    __shared__ float4 stag[D_DIM / 4];   // 3KB tag row

    const int t   = blockIdx.x;
    const int tid = threadIdx.x;

    if (tid < D_DIM / 4)
        stag[tid] = reinterpret_cast<const float4*>(h_tag + (size_t)t * D_DIM)[tid];
    __syncthreads();

    const int lane = tid & 31;
    const int warp = tid >> 5;
    const int pair = warp >> 1;          // 0..3 == sub-bin
    const int half = warp & 1;           // 0/1 == row half
    const int off  = half * 96 + lane;   // float4 offset base for this warp

    // tag half-row -> registers
    float4 ta0 = stag[off +  0];
    float4 ta1 = stag[off + 32];
    float4 ta2 = stag[off + 64];

    const int cidx = t * BIN_SUB + pair;
    int n = 0;
    if (lane == 0) n = g_cursor[cidx];   // READ ONLY (zero_kernel resets)
    n = __shfl_sync(0xffffffffu, n, 0);
    if (n > SUB_CAP) n = SUB_CAP;
    if (n == 0) return;

    const unsigned* elist = g_edges + (size_t)cidx * SUB_CAP;

    unsigned enc = elist[0];
    {
        const float4* b =
            reinterpret_cast<const float4*>(h_video + (size_t)(enc & 0x7fffffffu) * D_DIM);
        float4 v0 = b[off +  0];
        float4 v1 = b[off + 32];
        float4 v2 = b[off + 64];

        for (int e = 0; ; ) {
            const int enext = e + 1;
            const bool more = enext < n;

            // prefetch next edge's half-row during this edge's math
            unsigned enc_n = 0;
            float4 w0, w1, w2;
            if (more) {
                enc_n = elist[enext];
                const float4* bn =
                    reinterpret_cast<const float4*>(h_video + (size_t)(enc_n & 0x7fffffffu) * D_DIM);
                w0 = bn[off +  0];
                w1 = bn[off + 32];
                w2 = bn[off + 64];
            }

            float acc;
            acc  = ta0.x * v0.x + ta0.y * v0.y + ta0.z * v0.z + ta0.w * v0.w;
            acc += ta1.x * v1.x + ta1.y * v1.y + ta1.z * v1.z + ta1.w * v1.w;
            acc += ta2.x * v2.x + ta2.y * v2.y + ta2.z * v2.z + ta2.w * v2.w;

#pragma unroll
            for (int o = 16; o > 0; o >>= 1)
                acc += __shfl_xor_sync(0xffffffffu, acc, o);

            if (lane == 0) {
                int d = (int)(enc & 0x7fffffffu);
                size_t cell = (size_t)d * T_DIM + (size_t)t;
                atomicAdd(&cls[cell], acc);                       // partial dot
                if (half == 0 && (enc & 0x80000000u))
                    atomicAdd(&labels[cell], 1.0f);               // label once
            }

            if (!more) break;
            e = enext; enc = enc_n;
            v0 = w0; v1 = w1; v2 = w2;
        }
    }
}

// ---------------------------------------------------------------------------
extern "C" void kernel_launch(void* const* d_in, const int* in_sizes, int n_in,
                              void* d_out, int out_size)
{
    const float* h_tag   = (const float*)d_in[0];
    const float* h_video = (const float*)d_in[1];
    const int*   pos_src = (const int*)d_in[2];
    const int*   pos_dst = (const int*)d_in[3];
    const int*   neg_src = (const int*)d_in[4];
    const int*   neg_dst = (const int*)d_in[5];

    const int nPos = in_sizes[2];
    const int nNeg = in_sizes[4];
    const int nTot = nPos + nNeg;

    float* cls    = (float*)d_out;
    long long vt  = (long long)out_size / 2;
    float* labels = cls + vt;

    // 1) zero output + reset cursors (DRAM-write-bound)
    {
        long long nvec = (long long)out_size / 4;
        long long blocks = (nvec + 255) / 256;
        zero_kernel<<<(unsigned)blocks, 256>>>((float4*)d_out, nvec);
    }

    // 2) sub-binned scatter
    scatter_kernel<<<(nTot + 255) / 256, 256>>>(pos_src, pos_dst, neg_src, neg_dst,
                                                nPos, nTot);

    // 3) edge gather: warp-pair per edge, half-row per warp, prefetched
    edge_kernel<<<T_DIM, 256>>>(h_tag, h_video, cls, labels);
}

// round 14
// speedup vs baseline: 1.4714x; 1.4714x over previous
#include <cuda_runtime.h>
#include <cstdint>

// T = 2000 tags, V = 20000 videos, D = 768, E_POS = E_NEG = 100000
// Output layout: [cls_score (V*T f32), labels (V*T f32)]
//
// R14 = R3 structure verbatim (zero resets cursors -> scatter fills ->
// edge reads-only), with the edge kernel rebuilt around a cp.async smem
// pipeline: 2-stage ring per warp, 4 blocks/SM, 64 video rows in flight/SM.

#define D_DIM    768
#define T_DIM    2000
#define BIN_CAP  192      // edges/tag ~ Poisson(100); P(>192) ~ 1e-12
#define STAGES   2
#define ROW_F4   (D_DIM / 4)     // 192 float4 per row (3072 B)

__device__ int      g_cursor[T_DIM];
__device__ unsigned g_edges [T_DIM * BIN_CAP];  // bit31 = isPos, low = dst

// ---------------------------------------------------------------------------
__global__ void zero_kernel(float4* __restrict__ out, long long nvec) {
    long long i = (long long)blockIdx.x * blockDim.x + threadIdx.x;
    if (i < nvec)
        __stcs(&out[i], make_float4(0.f, 0.f, 0.f, 0.f));
    if (i < T_DIM) g_cursor[(int)i] = 0;   // reset cursors for this replay
}

// ---------------------------------------------------------------------------
__global__ void scatter_kernel(const int* __restrict__ pos_src,
                               const int* __restrict__ pos_dst,
                               const int* __restrict__ neg_src,
                               const int* __restrict__ neg_dst,
                               int nPos, int nTot) {
    int i = blockIdx.x * blockDim.x + threadIdx.x;
    if (i < nTot) {
        int t; unsigned enc;
        if (i < nPos) { t = pos_src[i];        enc = (unsigned)pos_dst[i] | 0x80000000u; }
        else          { t = neg_src[i - nPos]; enc = (unsigned)neg_dst[i - nPos]; }
        int slot = atomicAdd(&g_cursor[t], 1);
        if (slot < BIN_CAP)
            g_edges[t * BIN_CAP + slot] = enc;
    }
}

// ---------------------------------------------------------------------------
__device__ __forceinline__ uint32_t smem_u32(const void* p) {
    uint32_t a;
    asm("{ .reg .u64 tmp; cvta.to.shared.u64 tmp, %1; cvt.u32.u64 %0, tmp; }"
        : "=r"(a) : "l"(p));
    return a;
}
__device__ __forceinline__ void cp16(uint32_t dst, const void* src) {
    asm volatile("cp.async.cg.shared.global [%0], [%1], 16;"
                 :: "r"(dst), "l"(src));
}

// Issue the 6 cp.async for one video row (this lane's bytes: lane*16 + j*512)
__device__ __forceinline__ void issue_row(uint32_t sdst_base, const float* grow,
                                          int lane) {
    const char* src = reinterpret_cast<const char*>(grow) + lane * 16;
    uint32_t    dst = sdst_base + lane * 16;
#pragma unroll
    for (int j = 0; j < 6; j++)
        cp16(dst + j * 512, src + j * 512);
}

// ---------------------------------------------------------------------------
// Block per tag, 8 warps. Warp w handles edges w, w+8, ... with a private
// 2-stage cp.async ring (3KB/stage). Each lane copies exactly the bytes it
// later reads -> per-thread wait_group is sufficient, no warp barriers.
// Dynamic smem: 192 (tag) + 8*2*192 (ring) float4 = 52224 B -> 4 blocks/SM.
// ---------------------------------------------------------------------------
__global__ __launch_bounds__(256) void edge_kernel(
    const float* __restrict__ h_tag,
    const float* __restrict__ h_video,
    float*       __restrict__ cls,
    float*       __restrict__ labels)
{
    extern __shared__ float4 smem[];
    float4* stag = smem;                 // [0, 192)
    float4* ring = smem + ROW_F4;        // 16 stages of 192

    const int t    = blockIdx.x;
    const int tid  = threadIdx.x;
    const int lane = tid & 31;
    const int warp = tid >> 5;

    if (tid < ROW_F4)
        stag[tid] = reinterpret_cast<const float4*>(h_tag + (size_t)t * D_DIM)[tid];
    __syncthreads();

    // tag row -> registers
    float4 ta0 = stag[lane +   0];
    float4 ta1 = stag[lane +  32];
    float4 ta2 = stag[lane +  64];
    float4 ta3 = stag[lane +  96];
    float4 ta4 = stag[lane + 128];
    float4 ta5 = stag[lane + 160];

    int n = g_cursor[t];                 // READ ONLY (zero_kernel resets)
    if (n > BIN_CAP) n = BIN_CAP;

    const unsigned* elist = g_edges + (size_t)t * BIN_CAP;

    float4*  st0 = ring + (size_t)(warp * STAGES + 0) * ROW_F4;
    float4*  st1 = ring + (size_t)(warp * STAGES + 1) * ROW_F4;
    uint32_t sb0 = smem_u32(st0);
    uint32_t sb1 = smem_u32(st1);

    // prologue: fill both stages
    int nextE = warp;
#pragma unroll
    for (int s = 0; s < STAGES; s++) {
        if (nextE < n) {
            unsigned enc = elist[nextE];
            issue_row(s ? sb1 : sb0,
                      h_video + (size_t)(enc & 0x7fffffffu) * D_DIM, lane);
        }
        asm volatile("cp.async.commit_group;");
        nextE += 8;
    }

    int s = 0;
    for (int cur = warp; cur < n; cur += 8) {
        asm volatile("cp.async.wait_group 1;");   // oldest stage ready

        unsigned enc = elist[cur];
        const float4* B = s ? st1 : st0;
        float4 v0 = B[lane +   0];
        float4 v1 = B[lane +  32];
        float4 v2 = B[lane +  64];
        float4 v3 = B[lane +  96];
        float4 v4 = B[lane + 128];
        float4 v5 = B[lane + 160];

        float acc;
        acc  = ta0.x * v0.x + ta0.y * v0.y + ta0.z * v0.z + ta0.w * v0.w;
        acc += ta1.x * v1.x + ta1.y * v1.y + ta1.z * v1.z + ta1.w * v1.w;
        acc += ta2.x * v2.x + ta2.y * v2.y + ta2.z * v2.z + ta2.w * v2.w;
        acc += ta3.x * v3.x + ta3.y * v3.y + ta3.z * v3.z + ta3.w * v3.w;
        acc += ta4.x * v4.x + ta4.y * v4.y + ta4.z * v4.z + ta4.w * v4.w;
        acc += ta5.x * v5.x + ta5.y * v5.y + ta5.z * v5.z + ta5.w * v5.w;

#pragma unroll
        for (int o = 16; o > 0; o >>= 1)
            acc += __shfl_xor_sync(0xffffffffu, acc, o);

        if (lane == 0) {
            int d = (int)(enc & 0x7fffffffu);
            size_t cell = (size_t)d * T_DIM + (size_t)t;
            atomicAdd(&cls[cell], acc);
            if (enc & 0x80000000u) atomicAdd(&labels[cell], 1.0f);
        }

        // refill the stage we just consumed
        if (nextE < n) {
            unsigned enc_n = elist[nextE];
            issue_row(s ? sb1 : sb0,
                      h_video + (size_t)(enc_n & 0x7fffffffu) * D_DIM, lane);
        }
        asm volatile("cp.async.commit_group;");
        nextE += 8;
        s ^= 1;
    }

    asm volatile("cp.async.wait_all;");   // drain before smem is reused
}

// ---------------------------------------------------------------------------
extern "C" void kernel_launch(void* const* d_in, const int* in_sizes, int n_in,
                              void* d_out, int out_size)
{
    const float* h_tag   = (const float*)d_in[0];
    const float* h_video = (const float*)d_in[1];
    const int*   pos_src = (const int*)d_in[2];
    const int*   pos_dst = (const int*)d_in[3];
    const int*   neg_src = (const int*)d_in[4];
    const int*   neg_dst = (const int*)d_in[5];

    const int nPos = in_sizes[2];
    const int nNeg = in_sizes[4];
    const int nTot = nPos + nNeg;

    float* cls    = (float*)d_out;
    long long vt  = (long long)out_size / 2;
    float* labels = cls + vt;

    const int smem_bytes = (ROW_F4 + 8 * STAGES * ROW_F4) * sizeof(float4); // 52224

    // idempotent, host-side only (not captured as graph work)
    cudaFuncSetAttribute(edge_kernel,
                         cudaFuncAttributeMaxDynamicSharedMemorySize, smem_bytes);

    // 1) zero output + reset cursors (DRAM-write-bound, proven ~45us)
    {
        long long nvec = (long long)out_size / 4;
        long long blocks = (nvec + 255) / 256;
        zero_kernel<<<(unsigned)blocks, 256>>>((float4*)d_out, nvec);
    }

    // 2) bin edges by tag (proven)
    scatter_kernel<<<(nTot + 255) / 256, 256>>>(pos_src, pos_dst, neg_src, neg_dst,
                                                nPos, nTot);

    // 3) edge gather with cp.async pipeline
    edge_kernel<<<T_DIM, 256, smem_bytes>>>(h_tag, h_video, cls, labels);
}